// round 9
// baseline (speedup 1.0000x reference)
#include <cuda_runtime.h>
#include <cstdint>

// WCT: out[b] = alpha*x[b] + (1-alpha)*( M_b * (x[b]-mean_b) + mean_{perm[b]} )
// M_b = cov_{perm[b]}^{1/2} * cov_b^{-1/2}, roots via coupled Newton-Schulz.
// Folded: out = A_b * x + bias_b with A_b = alpha*I + (1-alpha)*M_b.
// R8: cp.async staging (no reg prefetch), 2 blocks/SM on gram+apply,
//     apply retiled to 128px/4px-per-thread with k-vectorized LDS.

#define BATCH 16
#define HW 65536
#define NCH 64
#define GBLK 16                 // gram blocks per batch
#define GPIX (HW / GBLK)        // 4096 pixels per gram block
#define ABLK 16                 // apply blocks per batch
#define APIX (HW / ABLK)        // 4096 pixels per apply block
#define NS_ITERS 6
#define MS 68                   // padded row stride (floats) for 64x64 smem matrices
#define XS 68                   // padded row stride (floats) for pixel tiles
#define GT 288                  // gram threads: 8 pixel-groups x 36 upper tiles
#define ATILE 128               // apply pixels per tile

// ---- device scratch (static globals; allocation-free) ----
__device__ float g_part[BATCH][GBLK][NCH * NCH];   // per-block gram partials
__device__ float g_psum[BATCH][GBLK][NCH];         // per-block channel-sum partials
__device__ float g_mean[BATCH][NCH];
__device__ float g_half[BATCH][NCH * NCH];         // cov^{1/2}
__device__ float g_invh[BATCH][NCH * NCH];         // cov^{-1/2}
__device__ float g_At  [BATCH][NCH * NCH];         // A^T: g_At[k*64+c] = A[c][k]
__device__ float g_bias[BATCH][NCH];

// ---- packed f32x2 helpers ----
__device__ __forceinline__ void ffma2(unsigned long long& d,
                                      unsigned long long a,
                                      unsigned long long b) {
    asm("fma.rn.f32x2 %0, %1, %2, %0;" : "+l"(d) : "l"(a), "l"(b));
}
__device__ __forceinline__ unsigned long long fadd2(unsigned long long a,
                                                    unsigned long long b) {
    unsigned long long r;
    asm("add.rn.f32x2 %0, %1, %2;" : "=l"(r) : "l"(a), "l"(b));
    return r;
}
__device__ __forceinline__ unsigned long long dup2f(float v) {
    unsigned long long r;
    unsigned u = __float_as_uint(v);
    asm("mov.b64 %0, {%1, %1};" : "=l"(r) : "r"(u));
    return r;
}
__device__ __forceinline__ float lo32(unsigned long long v) {
    return __uint_as_float((unsigned)v);
}
__device__ __forceinline__ float hi32(unsigned long long v) {
    return __uint_as_float((unsigned)(v >> 32));
}

// ---- cp.async helpers ----
__device__ __forceinline__ void cp16(uint32_t smem_dst, const void* gsrc) {
    asm volatile("cp.async.ca.shared.global [%0], [%1], 16;\n"
                 :: "r"(smem_dst), "l"(gsrc));
}
__device__ __forceinline__ void cp_commit() {
    asm volatile("cp.async.commit_group;\n" ::: "memory");
}
template <int N>
__device__ __forceinline__ void cp_wait() {
    asm volatile("cp.async.wait_group %0;\n" :: "n"(N) : "memory");
}
__device__ __forceinline__ uint32_t smem_u32(const void* p) {
    return (uint32_t)__cvta_generic_to_shared(p);
}

// ============================================================================
// Kernel 1: Gram + channel sums. grid (GBLK, BATCH), 288 threads, 2 blocks/SM.
// Symmetry: only 36 upper 8x8 tiles (8 pixel-groups x 36 threads), mirrored.
// cp.async double-buffered 64-pixel tiles.
// ============================================================================
__global__ void __launch_bounds__(GT, 2) gram_kernel(const float* __restrict__ x) {
    __shared__ float tile[2][64 * NCH];            // 2 x 16 KB ping-pong
    __shared__ float red[GT];
    __shared__ unsigned long long ssum2[64];

    const int b   = blockIdx.y;
    const int blk = blockIdx.x;
    const int tid = threadIdx.x;
    const int g   = tid / 36;          // pixel-interleave group 0..7
    const int u   = tid - g * 36;      // upper-triangle tile index 0..35

    // (ti, tj) with ti <= tj from triangle index u
    int r = u, ti = 0;
    while (r >= 8 - ti) { r -= 8 - ti; ++ti; }
    const int tj = ti + r;

    unsigned long long acc2[8][4];
#pragma unroll
    for (int i = 0; i < 8; i++)
#pragma unroll
        for (int j = 0; j < 4; j++) acc2[i][j] = 0ull;

    unsigned long long sum2 = 0ull;
    const int cp = tid & 31, ph = tid >> 5;

    const float4* x4 = reinterpret_cast<const float4*>(x) +
                       ((size_t)b * HW + (size_t)blk * GPIX) * (NCH / 4);
    const uint32_t t0s = smem_u32(tile[0]);
    const uint32_t t1s = smem_u32(tile[1]);

    // prologue: stage tile 0
#pragma unroll
    for (int rr = 0; rr < 4; ++rr) {
        int f = tid + GT * rr;
        if (f < 1024) cp16(t0s + f * 16, x4 + f);
    }
    cp_commit();

    for (int t = 0; t < GPIX / 64; ++t) {
        const int cb = t & 1;
        if (t + 1 < GPIX / 64) {
            const uint32_t dst = cb ? t0s : t1s;
#pragma unroll
            for (int rr = 0; rr < 4; ++rr) {
                int f = tid + GT * rr;
                if (f < 1024) cp16(dst + f * 16, x4 + (size_t)(t + 1) * 1024 + f);
            }
            cp_commit();
            cp_wait<1>();
        } else {
            cp_wait<0>();
        }
        __syncthreads();

        const float4*     t4c = reinterpret_cast<const float4*>(tile[cb]);
        const ulonglong2* tb2 = reinterpret_cast<const ulonglong2*>(tile[cb]);

#pragma unroll 4
        for (int p = g; p < 64; p += 8) {
            const float4 a0 = t4c[p * 16 + 2 * ti];
            const float4 a1 = t4c[p * 16 + 2 * ti + 1];
            const ulonglong2 b0 = tb2[p * 16 + 2 * tj];
            const ulonglong2 b1 = tb2[p * 16 + 2 * tj + 1];
            float av[8] = {a0.x, a0.y, a0.z, a0.w, a1.x, a1.y, a1.z, a1.w};
            unsigned long long bp[4] = {b0.x, b0.y, b1.x, b1.y};
#pragma unroll
            for (int i = 0; i < 8; i++) {
                unsigned long long ad = dup2f(av[i]);
#pragma unroll
                for (int j = 0; j < 4; j++) ffma2(acc2[i][j], ad, bp[j]);
            }
        }

        if (tid < 64) {
            const unsigned long long* tp =
                reinterpret_cast<const unsigned long long*>(tile[cb]);
#pragma unroll 8
            for (int p = ph; p < 64; p += 2)
                sum2 = fadd2(sum2, tp[p * 32 + cp]);
        }
        __syncthreads();     // all reads of tile[cb] done before next cp.async into it
    }

    // channel sums: combine the two pixel-halves
    if (tid < 64) ssum2[tid] = sum2;
    __syncthreads();
    if (tid < 32) {
        unsigned long long v = fadd2(ssum2[tid], ssum2[tid + 32]);
        g_psum[b][blk][2 * tid]     = lo32(v);
        g_psum[b][blk][2 * tid + 1] = hi32(v);
    }
    __syncthreads();

    // reduce acc over 8 pixel-groups; write tile and its mirror
#pragma unroll 1
    for (int e = 0; e < 64; ++e) {
        const int ii = e >> 3, jj = e & 7;
        const unsigned long long v2 = acc2[ii][jj >> 1];
        red[g * 36 + u] = (jj & 1) ? hi32(v2) : lo32(v2);
        __syncthreads();
        if (tid < 36) {
            float v = 0.f;
#pragma unroll
            for (int gg = 0; gg < 8; ++gg) v += red[gg * 36 + tid];
            const int row = 8 * ti + ii;
            const int col = 8 * tj + jj;
            g_part[b][blk][row * NCH + col] = v;
            g_part[b][blk][col * NCH + row] = v;   // symmetry (diag: same value)
        }
        __syncthreads();
    }
}

// ============================================================================
// 64x64 smem matmul helpers (stride MS), packed f32x2.
// ============================================================================
__device__ __forceinline__ void mm64p(const float* __restrict__ A,
                                      const float* __restrict__ B,
                                      unsigned long long r2[8], int i, int j0) {
#pragma unroll
    for (int q = 0; q < 8; q++) r2[q] = 0ull;
#pragma unroll 8
    for (int k = 0; k < 64; ++k) {
        unsigned long long ad = dup2f(A[i * MS + k]);
        const ulonglong2* b2 = reinterpret_cast<const ulonglong2*>(B + k * MS + j0);
        ulonglong2 x0 = b2[0], x1 = b2[1], x2 = b2[2], x3 = b2[3];
        ffma2(r2[0], ad, x0.x); ffma2(r2[1], ad, x0.y);
        ffma2(r2[2], ad, x1.x); ffma2(r2[3], ad, x1.y);
        ffma2(r2[4], ad, x2.x); ffma2(r2[5], ad, x2.y);
        ffma2(r2[6], ad, x3.x); ffma2(r2[7], ad, x3.y);
    }
}

__device__ __forceinline__ void mm64p8(const float* __restrict__ A,
                                       const float* __restrict__ B,
                                       unsigned long long r2[4], int i, int j0) {
#pragma unroll
    for (int q = 0; q < 4; q++) r2[q] = 0ull;
#pragma unroll 8
    for (int k = 0; k < 64; ++k) {
        unsigned long long ad = dup2f(A[i * MS + k]);
        const ulonglong2* b2 = reinterpret_cast<const ulonglong2*>(B + k * MS + j0);
        ulonglong2 x0 = b2[0], x1 = b2[1];
        ffma2(r2[0], ad, x0.x); ffma2(r2[1], ad, x0.y);
        ffma2(r2[2], ad, x1.x); ffma2(r2[3], ad, x1.y);
    }
}

// ============================================================================
// Kernel 2: fused cov-reduction + Newton-Schulz. grid BATCH, 512 threads.
// ============================================================================
__global__ void __launch_bounds__(512) ns_kernel() {
    extern __shared__ float dsm[];
    float* sY = dsm;
    float* sZ = sY + 64 * MS;
    float* sT = sZ + 64 * MS;
    __shared__ float mean_s[NCH];

    const int b = blockIdx.x, tid = threadIdx.x;
    const int i8  = tid >> 3, j8 = (tid & 7) * 8;            // T-phase mapping
    const int u   = tid & 255;
    const int i16 = u >> 2, j16 = (u & 3) * 16;              // half-phase mapping

    if (tid < NCH) {
        float s = 0.f;
#pragma unroll
        for (int k = 0; k < GBLK; ++k) s += g_psum[b][k][tid];
        float m = s * (1.f / (float)HW);
        mean_s[tid] = m;
        g_mean[b][tid] = m;
    }
    __syncthreads();

    const float inv_d = 1.f / (float)(HW - 1);
    for (int e = tid; e < 4096; e += 512) {
        float s = 0.f;
#pragma unroll
        for (int k = 0; k < GBLK; ++k) s += g_part[b][k][e];
        int i = e >> 6, j = e & 63;
        sZ[i * MS + j] = (s - (float)HW * mean_s[i] * mean_s[j]) * inv_d;
    }
    __syncthreads();

    if (tid < 64) {
        float s = 0.f;
        for (int j = 0; j < 64; ++j) s += fabsf(sZ[tid * MS + j]);
        sY[tid] = s;
    }
    __syncthreads();
    if (tid == 0) {
        float m = 0.f;
        for (int r = 0; r < 64; ++r) m = fmaxf(m, sY[r]);
        sT[0] = m;
    }
    __syncthreads();
    const float c = sT[0];
    const float inv_c = 1.f / c;
    __syncthreads();

    for (int e = tid; e < 4096; e += 512) {
        int r = e >> 6, q = e & 63;
        float v = sZ[r * MS + q];
        sY[r * MS + q] = v * inv_c;
        sZ[r * MS + q] = (r == q) ? 1.f : 0.f;
    }
    __syncthreads();

    for (int it = 0; it < NS_ITERS; ++it) {
        unsigned long long t2[4];
        mm64p8(sZ, sY, t2, i8, j8);
#pragma unroll
        for (int q = 0; q < 4; q++) {
            int j = j8 + 2 * q;
            sT[i8 * MS + j]     = ((i8 == j)     ? 1.5f : 0.f) - 0.5f * lo32(t2[q]);
            sT[i8 * MS + j + 1] = ((i8 == j + 1) ? 1.5f : 0.f) - 0.5f * hi32(t2[q]);
        }
        __syncthreads();

        unsigned long long r2[8];
        if (tid < 256) mm64p(sY, sT, r2, i16, j16);
        else           mm64p(sT, sZ, r2, i16, j16);
        __syncthreads();
        float* dst = (tid < 256) ? sY : sZ;
#pragma unroll
        for (int q = 0; q < 8; q++) {
            dst[i16 * MS + j16 + 2 * q]     = lo32(r2[q]);
            dst[i16 * MS + j16 + 2 * q + 1] = hi32(r2[q]);
        }
        __syncthreads();
    }

    const float sc = sqrtf(c), isc = rsqrtf(c);
    for (int e = tid; e < 4096; e += 512) {
        int r = e >> 6, q = e & 63;
        g_half[b][e] = sY[r * MS + q] * sc;
        g_invh[b][e] = sZ[r * MS + q] * isc;
    }
}

// ============================================================================
// Kernel 3: A_b = alpha I + (1-alpha) * half[perm[b]] * invh[b] (stored A^T),
//           bias_b = (1-alpha)*(mean[perm[b]] - M*mean[b]). grid BATCH, 512.
// ============================================================================
__global__ void __launch_bounds__(512) comb_kernel(const int* __restrict__ perm,
                                                   const float* __restrict__ alpha) {
    __shared__ float sS[64 * MS], sTi[64 * MS], red[512];
    const int b = blockIdx.x, tid = threadIdx.x;
    const int pb = perm[b];
    const float al = alpha[b];
    const float oma = 1.f - al;

    for (int e = tid; e < 4096; e += 512) {
        int r = e >> 6, q = e & 63;
        sS [r * MS + q] = g_half[pb][e];
        sTi[r * MS + q] = g_invh[b][e];
    }
    __syncthreads();

    const int i = tid >> 3, j0 = (tid & 7) * 8;
    unsigned long long m2[4];
    mm64p8(sS, sTi, m2, i, j0);   // M[i][j0..j0+7]

    float m[8];
#pragma unroll
    for (int q = 0; q < 4; q++) { m[2 * q] = lo32(m2[q]); m[2 * q + 1] = hi32(m2[q]); }

    float pdot = 0.f;
#pragma unroll
    for (int q = 0; q < 8; q++) {
        int j = j0 + q;
        g_At[b][j * 64 + i] = ((i == j) ? al : 0.f) + oma * m[q];  // A^T[j][i]=A[i][j]
        pdot += m[q] * g_mean[b][j];
    }
    red[tid] = pdot;
    __syncthreads();
    if (tid < 64) {
        float dot = 0.f;
#pragma unroll
        for (int t = 0; t < 8; t++) dot += red[tid * 8 + t];
        g_bias[b][tid] = oma * (g_mean[pb][tid] - dot);
    }
}

// ============================================================================
// Kernel 4: out[p] = A*x[p] + bias. grid (ABLK, BATCH), 256 threads,
// 2 blocks/SM. 128-pixel double-buffered cp.async tiles; thread = 4px x 8ch.
// Inner loop vectorized over k (float4 LDS of x, 4 k-steps per iteration).
// Dynamic smem: 2*128*XS + 4096 + 64 floats (~86 KB).
// ============================================================================
__global__ void __launch_bounds__(256, 2) apply_kernel(const float* __restrict__ x,
                                                       float* __restrict__ out) {
    extern __shared__ float dsm[];
    float* sx0 = dsm;                      // 128 * XS
    float* sx1 = sx0 + ATILE * XS;         // 128 * XS
    float* sA  = sx1 + ATILE * XS;         // 64*64 (A^T, row k contiguous in c)
    float* sb  = sA + 4096;                // 64

    const int b = blockIdx.y, blk = blockIdx.x, tid = threadIdx.x;

    for (int e = tid; e < 4096; e += 256) sA[e] = g_At[b][e];
    if (tid < 64) sb[tid] = g_bias[b][tid];

    const int ci = tid & 7;          // channel group: c0 = 8*ci
    const int pi = tid >> 3;         // pixel slot 0..31 ; pixels pi + 32*s, s<4
    const int c0 = ci * 8;

    const float4* x4 = reinterpret_cast<const float4*>(x) +
                       ((size_t)b * HW + (size_t)blk * APIX) * (NCH / 4);
    float4* o4 = reinterpret_cast<float4*>(out) +
                 ((size_t)b * HW + (size_t)blk * APIX) * (NCH / 4);
    const ulonglong2* sA2 = reinterpret_cast<const ulonglong2*>(sA);
    const unsigned long long* sb2 =
        reinterpret_cast<const unsigned long long*>(sb + c0);
    const uint32_t s0 = smem_u32(sx0);
    const uint32_t s1 = smem_u32(sx1);

    // stage tile 0: 128 px * 16 float4 = 2048 chunks, 8 per thread
#pragma unroll
    for (int k2 = 0; k2 < 8; ++k2) {
        int f = tid + 256 * k2;
        int p = f >> 4, q = f & 15;
        cp16(s0 + (p * XS + q * 4) * 4, x4 + f);
    }
    cp_commit();

    const int NT = APIX / ATILE;     // 32 tiles
    for (int t = 0; t < NT; ++t) {
        const int cb = t & 1;
        if (t + 1 < NT) {
            const uint32_t dst = cb ? s0 : s1;
#pragma unroll
            for (int k2 = 0; k2 < 8; ++k2) {
                int f = tid + 256 * k2;
                int p = f >> 4, q = f & 15;
                cp16(dst + (p * XS + q * 4) * 4, x4 + (size_t)(t + 1) * 2048 + f);
            }
            cp_commit();
            cp_wait<1>();
        } else {
            cp_wait<0>();
        }
        __syncthreads();

        const float* sx = cb ? sx1 : sx0;
        const float4* sxv = reinterpret_cast<const float4*>(sx);

        unsigned long long acc2[4][4];
#pragma unroll
        for (int s = 0; s < 4; s++)
#pragma unroll
            for (int j = 0; j < 4; j++) acc2[s][j] = sb2[j];

#pragma unroll 4
        for (int k4 = 0; k4 < 16; ++k4) {
            ulonglong2 ap[4];
#pragma unroll
            for (int kk = 0; kk < 4; ++kk) {
                // rows k=4*k4+kk of A^T: 8 channels starting at c0
                ap[kk] = sA2[(4 * k4 + kk) * 16 + 2 * ci];
            }
            ulonglong2 aq[4];
#pragma unroll
            for (int kk = 0; kk < 4; ++kk)
                aq[kk] = sA2[(4 * k4 + kk) * 16 + 2 * ci + 1];

#pragma unroll
            for (int s = 0; s < 4; s++) {
                const float4 xv = sxv[(pi + 32 * s) * (XS / 4) + k4];
                float xk[4] = {xv.x, xv.y, xv.z, xv.w};
#pragma unroll
                for (int kk = 0; kk < 4; ++kk) {
                    unsigned long long xd = dup2f(xk[kk]);
                    ffma2(acc2[s][0], xd, ap[kk].x);
                    ffma2(acc2[s][1], xd, ap[kk].y);
                    ffma2(acc2[s][2], xd, aq[kk].x);
                    ffma2(acc2[s][3], xd, aq[kk].y);
                }
            }
        }
        __syncthreads();   // done reading sx[cb] before next cp.async overwrites it

#pragma unroll
        for (int s = 0; s < 4; s++) {
            int p = pi + 32 * s;
            o4[(size_t)t * 2048 + p * 16 + 2 * ci] =
                make_float4(lo32(acc2[s][0]), hi32(acc2[s][0]),
                            lo32(acc2[s][1]), hi32(acc2[s][1]));
            o4[(size_t)t * 2048 + p * 16 + 2 * ci + 1] =
                make_float4(lo32(acc2[s][2]), hi32(acc2[s][2]),
                            lo32(acc2[s][3]), hi32(acc2[s][3]));
        }
    }
}

// ============================================================================
extern "C" void kernel_launch(void* const* d_in, const int* in_sizes, int n_in,
                              void* d_out, int out_size) {
    (void)in_sizes; (void)n_in; (void)out_size;
    const float* x     = (const float*)d_in[0];
    const int*   perm  = (const int*)d_in[1];
    const float* alpha = (const float*)d_in[2];
    float*       out   = (float*)d_out;

    const int ns_smem    = 3 * 64 * MS * (int)sizeof(float);                   // 52224 B
    const int apply_smem = (2 * ATILE * XS + 4096 + 64) * (int)sizeof(float);  // 86272 B
    cudaFuncSetAttribute(ns_kernel, cudaFuncAttributeMaxDynamicSharedMemorySize, ns_smem);
    cudaFuncSetAttribute(apply_kernel, cudaFuncAttributeMaxDynamicSharedMemorySize, apply_smem);

    gram_kernel<<<dim3(GBLK, BATCH), GT>>>(x);
    ns_kernel<<<BATCH, 512, ns_smem>>>();
    comb_kernel<<<BATCH, 512>>>(perm, alpha);
    apply_kernel<<<dim3(ABLK, BATCH), 256, apply_smem>>>(x, out);
}